// round 6
// baseline (speedup 1.0000x reference)
#include <cuda_runtime.h>
#include <cuda_bf16.h>
#include <mma.h>
#include <math_constants.h>

using namespace nvcuda;

// Problem constants
#define BB 2
#define S  2048
#define DD 1024
#define H  16
#define HD 64
#define BH (BB*H)       // 32
#define MROWS (BB*S)    // 4096
#define MASK_N (BB*S*S) // 8,388,608

// Scratch (device globals: allocation-free)
__device__ __nv_bfloat16 g_qh[BH * S * HD];
__device__ __nv_bfloat16 g_ql[BH * S * HD];
__device__ __nv_bfloat16 g_kh[BH * S * HD];
__device__ __nv_bfloat16 g_kl[BH * S * HD];
__device__ __nv_bfloat16 g_vh[BH * S * HD];
__device__ __nv_bfloat16 g_vl[BH * S * HD];
__device__ float g_rowsum[BH * S];
__device__ unsigned char g_mask_u8[MASK_N];
__device__ int g_mask_mode;
__device__ float g_attn_scratch[(size_t)BH * S * S]; // fallback if d_out only holds ctx

// ---------------------------------------------------------------------------
// exp2 on the FMA pipe. Input y = score * log2(e) (scale folded into Q).
// 6-FMA poly on f in [-0.5, 0.5]; rel err ~1e-8.
// ---------------------------------------------------------------------------
__device__ __forceinline__ float fast_exp2(float y) {
    y = fminf(fmaxf(y, -126.0f), 126.0f);
    float r = rintf(y);
    float f = y - r;                                   // exact
    float p = 1.5403530393381606e-4f;                  // ln2^6/720
    p = fmaf(p, f, 1.3333558146428443e-3f);            // ln2^5/120
    p = fmaf(p, f, 9.6181291076284770e-3f);            // ln2^4/24
    p = fmaf(p, f, 5.5504108664821580e-2f);            // ln2^3/6
    p = fmaf(p, f, 2.4022650695910100e-1f);            // ln2^2/2
    p = fmaf(p, f, 6.9314718055994530e-1f);            // ln2
    p = fmaf(p, f, 1.0f);
    return p * __int_as_float(((int)r + 127) << 23);   // * 2^r
}

__device__ __forceinline__ void split_bf(float x, __nv_bfloat16& h, __nv_bfloat16& l) {
    h = __float2bfloat16(x);
    l = __float2bfloat16(x - __bfloat162float(h));
}
__device__ __forceinline__ unsigned pack2(__nv_bfloat16 a, __nv_bfloat16 b) {
    __nv_bfloat162 t; t.x = a; t.y = b;
    return *(unsigned*)&t;
}

// ---------------------------------------------------------------------------
// Mask dtype detection + conversion (proven R2-R4)
// ---------------------------------------------------------------------------
__global__ void detect_mask_kernel(const unsigned int* __restrict__ w) {
    __shared__ int s_int, s_float;
    if (threadIdx.x == 0) { s_int = 1; s_float = 1; }
    __syncthreads();
    int li = 1, lf = 1;
    for (int i = threadIdx.x; i < 2048; i += 256) {
        unsigned int x = w[i];
        if (x != 0u && x != 1u) li = 0;
        if (x != 0u && x != 0x3f800000u) lf = 0;
    }
    if (!li) atomicAnd(&s_int, 0);
    if (!lf) atomicAnd(&s_float, 0);
    __syncthreads();
    if (threadIdx.x == 0) g_mask_mode = s_int ? 1 : (s_float ? 2 : 0);
}

__global__ void convert_mask_kernel(const void* __restrict__ mraw,
                                    unsigned char* __restrict__ mu8) {
    int i = blockIdx.x * blockDim.x + threadIdx.x;
    if (i >= MASK_N) return;
    int mode = g_mask_mode;
    unsigned char v;
    if (mode == 0)      v = ((const unsigned char*)mraw)[i];
    else if (mode == 1) v = (unsigned char)(((const int*)mraw)[i] != 0);
    else                v = (unsigned char)(((const float*)mraw)[i] != 0.0f);
    mu8[i] = v;
}

// ---------------------------------------------------------------------------
// Projection (all 3 via z): C = X*W^T + bias, *scale, split bf16 hi/lo,
// head-split layout. Q gets scale = 0.125*log2(e) (exp2 folding).
// ---------------------------------------------------------------------------
__global__ void __launch_bounds__(256, 2)
proj_wmma(const float* __restrict__ X0, const float* __restrict__ X1, const float* __restrict__ X2,
          const float* __restrict__ W0, const float* __restrict__ W1, const float* __restrict__ W2,
          const float* __restrict__ B0, const float* __restrict__ B1, const float* __restrict__ B2,
          __nv_bfloat16* __restrict__ Oh0, __nv_bfloat16* __restrict__ Ol0,
          __nv_bfloat16* __restrict__ Oh1, __nv_bfloat16* __restrict__ Ol1,
          __nv_bfloat16* __restrict__ Oh2, __nv_bfloat16* __restrict__ Ol2) {
    extern __shared__ char smraw[];
    __nv_bfloat16* sAh = (__nv_bfloat16*)smraw;        // [128][40]
    __nv_bfloat16* sAl = sAh + 128 * 40;
    __nv_bfloat16* sBh = sAl + 128 * 40;
    __nv_bfloat16* sBl = sBh + 128 * 40;
    float* sC = (float*)smraw;                         // [128][136] (aliased)

    const float *X, *W, *Bv; __nv_bfloat16 *Oh, *Ol; float scale;
    if (blockIdx.z == 0)      { X = X0; W = W0; Bv = B0; Oh = Oh0; Ol = Ol0;
                                scale = 0.18033688011111378f; }   // 0.125*log2(e)
    else if (blockIdx.z == 1) { X = X1; W = W1; Bv = B1; Oh = Oh1; Ol = Ol1; scale = 1.0f; }
    else                      { X = X2; W = W2; Bv = B2; Oh = Oh2; Ol = Ol2; scale = 1.0f; }

    const int tid = threadIdx.x;
    const int warp = tid >> 5, wm = warp >> 1, wn = warp & 1;
    const int m0 = blockIdx.y * 128, n0 = blockIdx.x * 128;
    const int lr = tid >> 3, lc = tid & 7;

    wmma::fragment<wmma::accumulator, 16, 16, 16, float> acc[2][4];
#pragma unroll
    for (int i = 0; i < 2; i++)
#pragma unroll
        for (int j = 0; j < 4; j++) wmma::fill_fragment(acc[i][j], 0.0f);

    for (int k0 = 0; k0 < DD; k0 += 32) {
#pragma unroll
        for (int it = 0; it < 4; it++) {
            int r = lr + it * 32;
            float4 xv = *(const float4*)(X + (size_t)(m0 + r) * DD + k0 + lc * 4);
            float4 wv = *(const float4*)(W + (size_t)(n0 + r) * DD + k0 + lc * 4);
            int sa = r * 40 + lc * 4;
            float xs[4] = {xv.x, xv.y, xv.z, xv.w};
            float ws[4] = {wv.x, wv.y, wv.z, wv.w};
#pragma unroll
            for (int j = 0; j < 4; j++) {
                __nv_bfloat16 h, l;
                split_bf(xs[j], h, l); sAh[sa + j] = h; sAl[sa + j] = l;
                split_bf(ws[j], h, l); sBh[sa + j] = h; sBl[sa + j] = l;
            }
        }
        __syncthreads();
#pragma unroll
        for (int kk = 0; kk < 32; kk += 16) {
            wmma::fragment<wmma::matrix_a, 16, 16, 16, __nv_bfloat16, wmma::row_major> ah[2], al[2];
#pragma unroll
            for (int i = 0; i < 2; i++) {
                wmma::load_matrix_sync(ah[i], sAh + (wm * 32 + i * 16) * 40 + kk, 40);
                wmma::load_matrix_sync(al[i], sAl + (wm * 32 + i * 16) * 40 + kk, 40);
            }
#pragma unroll
            for (int j = 0; j < 4; j++) {
                wmma::fragment<wmma::matrix_b, 16, 16, 16, __nv_bfloat16, wmma::col_major> bh_, bl_;
                wmma::load_matrix_sync(bh_, sBh + (wn * 64 + j * 16) * 40 + kk, 40);
                wmma::load_matrix_sync(bl_, sBl + (wn * 64 + j * 16) * 40 + kk, 40);
#pragma unroll
                for (int i = 0; i < 2; i++) {
                    wmma::mma_sync(acc[i][j], ah[i], bh_, acc[i][j]);
                    wmma::mma_sync(acc[i][j], ah[i], bl_, acc[i][j]);
                    wmma::mma_sync(acc[i][j], al[i], bh_, acc[i][j]);
                }
            }
        }
        __syncthreads();
    }

#pragma unroll
    for (int i = 0; i < 2; i++)
#pragma unroll
        for (int j = 0; j < 4; j++)
            wmma::store_matrix_sync(sC + (wm * 32 + i * 16) * 136 + wn * 64 + j * 16,
                                    acc[i][j], 136, wmma::mem_row_major);
    __syncthreads();

#pragma unroll
    for (int it = 0; it < 16; it++) {
        int idx = tid + it * 256;
        int r = idx >> 5, c4 = (idx & 31) * 4;
        float4 v = *(float4*)&sC[r * 136 + c4];
        float4 bb = *(const float4*)&Bv[n0 + c4];
        float o[4] = {(v.x + bb.x) * scale, (v.y + bb.y) * scale,
                      (v.z + bb.z) * scale, (v.w + bb.w) * scale};
        int gc = n0 + c4;
        int hh = gc >> 6, d = gc & 63;
        int gr = m0 + r;
        int b = gr >> 11, s = gr & (S - 1);
        size_t p = (((size_t)(b * H + hh)) * S + s) * HD + d;
        __nv_bfloat16 oh[4], ol[4];
#pragma unroll
        for (int j = 0; j < 4; j++) split_bf(o[j], oh[j], ol[j]);
        uint2 uh, ul;
        uh.x = pack2(oh[0], oh[1]); uh.y = pack2(oh[2], oh[3]);
        ul.x = pack2(ol[0], ol[1]); ul.y = pack2(ol[2], ol[3]);
        *(uint2*)&Oh[p] = uh;
        *(uint2*)&Ol[p] = ul;
    }
}

// ---------------------------------------------------------------------------
// Scores: 128q x 128k tile, d=64 resident. Writes e = mask ? 0 : exp2(Q'.K)
// as RAW fp32 straight into the attn buffer; atomic rowsums. No split/pack.
// ---------------------------------------------------------------------------
__global__ void __launch_bounds__(256, 2)
scores_wmma(const __nv_bfloat16* __restrict__ Qh, const __nv_bfloat16* __restrict__ Ql,
            const __nv_bfloat16* __restrict__ Kh, const __nv_bfloat16* __restrict__ Kl,
            const unsigned char* __restrict__ mask,
            float* __restrict__ attn, float* __restrict__ rowsum) {
    extern __shared__ char smraw[];
    __nv_bfloat16* sQh = (__nv_bfloat16*)smraw;        // [128][72]
    __nv_bfloat16* sQl = sQh + 128 * 72;
    __nv_bfloat16* sKh = sQl + 128 * 72;
    __nv_bfloat16* sKl = sKh + 128 * 72;
    float* sC = (float*)smraw;                          // [128][136] (aliased)

    const int tid = threadIdx.x;
    const int warp = tid >> 5, wm = warp >> 1, wn = warp & 1;
    const int bh = blockIdx.z;
    const int q0 = blockIdx.y * 128, k0 = blockIdx.x * 128;
    const size_t qb = (size_t)bh * S * HD;
    const int lr = tid >> 3, lc = tid & 7;

#pragma unroll
    for (int it = 0; it < 4; it++) {
        int r = lr + it * 32;
        *(uint4*)&sQh[r * 72 + lc * 8] = *(const uint4*)&Qh[qb + (size_t)(q0 + r) * HD + lc * 8];
        *(uint4*)&sQl[r * 72 + lc * 8] = *(const uint4*)&Ql[qb + (size_t)(q0 + r) * HD + lc * 8];
        *(uint4*)&sKh[r * 72 + lc * 8] = *(const uint4*)&Kh[qb + (size_t)(k0 + r) * HD + lc * 8];
        *(uint4*)&sKl[r * 72 + lc * 8] = *(const uint4*)&Kl[qb + (size_t)(k0 + r) * HD + lc * 8];
    }
    __syncthreads();

    wmma::fragment<wmma::accumulator, 16, 16, 16, float> acc[2][4];
#pragma unroll
    for (int i = 0; i < 2; i++)
#pragma unroll
        for (int j = 0; j < 4; j++) wmma::fill_fragment(acc[i][j], 0.0f);

#pragma unroll
    for (int kk = 0; kk < 64; kk += 16) {
        wmma::fragment<wmma::matrix_a, 16, 16, 16, __nv_bfloat16, wmma::row_major> ah[2], al[2];
#pragma unroll
        for (int i = 0; i < 2; i++) {
            wmma::load_matrix_sync(ah[i], sQh + (wm * 32 + i * 16) * 72 + kk, 72);
            wmma::load_matrix_sync(al[i], sQl + (wm * 32 + i * 16) * 72 + kk, 72);
        }
#pragma unroll
        for (int j = 0; j < 4; j++) {
            wmma::fragment<wmma::matrix_b, 16, 16, 16, __nv_bfloat16, wmma::col_major> bh_, bl_;
            wmma::load_matrix_sync(bh_, sKh + (wn * 64 + j * 16) * 72 + kk, 72);
            wmma::load_matrix_sync(bl_, sKl + (wn * 64 + j * 16) * 72 + kk, 72);
#pragma unroll
            for (int i = 0; i < 2; i++) {
                wmma::mma_sync(acc[i][j], ah[i], bh_, acc[i][j]);
                wmma::mma_sync(acc[i][j], ah[i], bl_, acc[i][j]);
                wmma::mma_sync(acc[i][j], al[i], bh_, acc[i][j]);
            }
        }
    }
    __syncthreads();

#pragma unroll
    for (int i = 0; i < 2; i++)
#pragma unroll
        for (int j = 0; j < 4; j++)
            wmma::store_matrix_sync(sC + (wm * 32 + i * 16) * 136 + wn * 64 + j * 16,
                                    acc[i][j], 136, wmma::mem_row_major);
    __syncthreads();

    const unsigned char* mb = mask + (size_t)(bh & (BB - 1)) * S * S;
    float* ab = attn + (size_t)bh * S * S;
#pragma unroll
    for (int it = 0; it < 16; it++) {
        int idx = tid + it * 256;
        int r = idx >> 5, c4 = (idx & 31) * 4;
        int q = q0 + r, kc = k0 + c4;
        float4 v = *(float4*)&sC[r * 136 + c4];
        uchar4 m4 = *(const uchar4*)&mb[(size_t)q * S + kc];
        float e0 = m4.x ? 0.0f : fast_exp2(v.x);
        float e1 = m4.y ? 0.0f : fast_exp2(v.y);
        float e2 = m4.z ? 0.0f : fast_exp2(v.z);
        float e3 = m4.w ? 0.0f : fast_exp2(v.w);
        *(float4*)&ab[(size_t)q * S + kc] = make_float4(e0, e1, e2, e3);
        float rs = (e0 + e1) + (e2 + e3);
#pragma unroll
        for (int o = 16; o > 0; o >>= 1) rs += __shfl_xor_sync(0xffffffffu, rs, o);
        if ((tid & 31) == 0) atomicAdd(&rowsum[bh * S + q], rs);
    }
}

// ---------------------------------------------------------------------------
// AV: a = e * (1/rowsum); write a (final attn, in place); split a -> smem
// hi/lo; ctx = a @ V via wmma, direct global store. K-step 64.
// ---------------------------------------------------------------------------
__global__ void __launch_bounds__(256, 2)
av_wmma(const __nv_bfloat16* __restrict__ Vh, const __nv_bfloat16* __restrict__ Vl,
        const float* __restrict__ rowsum,
        float* __restrict__ attn, float* __restrict__ ctx) {
    extern __shared__ char smraw[];
    __nv_bfloat16* sAh = (__nv_bfloat16*)smraw;     // [128][72] (cols 0..63 used)
    __nv_bfloat16* sAl = sAh + 128 * 72;
    __nv_bfloat16* sVh = sAl + 128 * 72;            // [64][72]
    __nv_bfloat16* sVl = sVh + 64 * 72;
    __shared__ float rr[128];

    const int tid = threadIdx.x;
    const int warp = tid >> 5, wm = warp >> 2, wn = warp & 3;  // 2 x 4 warps
    const int bh = blockIdx.y, q0 = blockIdx.x * 128;
    const int b = bh >> 4, h = bh & 15;
    const size_t vb = (size_t)bh * S * HD;
    float* ab = attn + (size_t)bh * S * S;   // block-local base; offsets below are LOCAL

    if (tid < 128) rr[tid] = 1.0f / rowsum[bh * S + q0 + tid];
    __syncthreads();

    // warp tile: wm in {0,1} -> 64 q rows each, wn in {0..3} -> 16 d cols each.
    wmma::fragment<wmma::accumulator, 16, 16, 16, float> acc[4];
#pragma unroll
    for (int i = 0; i < 4; i++) wmma::fill_fragment(acc[i], 0.0f);

    for (int k0 = 0; k0 < S; k0 += 64) {
        // A: 128q x 64k. 2048 float4 slots, 8 per thread.
#pragma unroll
        for (int it = 0; it < 8; it++) {
            int slot = tid + it * 256;
            int r = slot >> 4, c4 = (slot & 15) * 4;
            size_t p = (size_t)(q0 + r) * S + k0 + c4;   // LOCAL offset (bug fixed)
            float4 e4 = *(const float4*)&ab[p];
            float rrq = rr[r];
            float a0 = e4.x * rrq, a1 = e4.y * rrq, a2 = e4.z * rrq, a3 = e4.w * rrq;
            *(float4*)&ab[p] = make_float4(a0, a1, a2, a3);  // final attn
            __nv_bfloat16 h0, l0, h1, l1, h2, l2, h3, l3;
            split_bf(a0, h0, l0); split_bf(a1, h1, l1);
            split_bf(a2, h2, l2); split_bf(a3, h3, l3);
            uint2 sh, sl;
            sh.x = pack2(h0, h1); sh.y = pack2(h2, h3);
            sl.x = pack2(l0, l1); sl.y = pack2(l2, l3);
            *(uint2*)&sAh[r * 72 + c4] = sh;
            *(uint2*)&sAl[r * 72 + c4] = sl;
        }
        // V: 64k x 64d, uint4 (8 bf16) per access
#pragma unroll
        for (int it = 0; it < 2; it++) {
            int slot = tid + it * 256;
            int r = slot >> 3, c8 = (slot & 7) * 8;
            *(uint4*)&sVh[r * 72 + c8] = *(const uint4*)&Vh[vb + (size_t)(k0 + r) * HD + c8];
            *(uint4*)&sVl[r * 72 + c8] = *(const uint4*)&Vl[vb + (size_t)(k0 + r) * HD + c8];
        }
        __syncthreads();
#pragma unroll
        for (int kk = 0; kk < 64; kk += 16) {
            wmma::fragment<wmma::matrix_b, 16, 16, 16, __nv_bfloat16, wmma::row_major> bh_, bl_;
            wmma::load_matrix_sync(bh_, sVh + kk * 72 + wn * 16, 72);
            wmma::load_matrix_sync(bl_, sVl + kk * 72 + wn * 16, 72);
#pragma unroll
            for (int i = 0; i < 4; i++) {
                wmma::fragment<wmma::matrix_a, 16, 16, 16, __nv_bfloat16, wmma::row_major> ah, al;
                wmma::load_matrix_sync(ah, sAh + (wm * 64 + i * 16) * 72 + kk, 72);
                wmma::load_matrix_sync(al, sAl + (wm * 64 + i * 16) * 72 + kk, 72);
                wmma::mma_sync(acc[i], ah, bh_, acc[i]);
                wmma::mma_sync(acc[i], ah, bl_, acc[i]);
                wmma::mma_sync(acc[i], al, bh_, acc[i]);
            }
        }
        __syncthreads();
    }

#pragma unroll
    for (int i = 0; i < 4; i++) {
        int m = q0 + wm * 64 + i * 16;
        int n = wn * 16;
        float* p = ctx + ((size_t)b * S + m) * DD + h * HD + n;
        wmma::store_matrix_sync(p, acc[i], DD, wmma::mem_row_major);
    }
}

// ---------------------------------------------------------------------------
extern "C" void kernel_launch(void* const* d_in, const int* in_sizes, int n_in,
                              void* d_out, int out_size) {
    const float* query = (const float*)d_in[0];
    const float* key   = (const float*)d_in[1];
    const float* value = (const float*)d_in[2];
    const void*  mask  = d_in[3];
    const float* Wq = (const float*)d_in[4];
    const float* bq = (const float*)d_in[5];
    const float* Wk = (const float*)d_in[6];
    const float* bk = (const float*)d_in[7];
    const float* Wv = (const float*)d_in[8];
    const float* bv = (const float*)d_in[9];

    float* ctx = (float*)d_out;

    __nv_bfloat16 *qh, *ql, *kh, *kl, *vh, *vl;
    float *rowsum, *attn_fallback;
    unsigned char* mu8;
    cudaGetSymbolAddress((void**)&qh, g_qh);
    cudaGetSymbolAddress((void**)&ql, g_ql);
    cudaGetSymbolAddress((void**)&kh, g_kh);
    cudaGetSymbolAddress((void**)&kl, g_kl);
    cudaGetSymbolAddress((void**)&vh, g_vh);
    cudaGetSymbolAddress((void**)&vl, g_vl);
    cudaGetSymbolAddress((void**)&mu8, g_mask_u8);
    cudaGetSymbolAddress((void**)&rowsum, g_rowsum);
    cudaGetSymbolAddress((void**)&attn_fallback, g_attn_scratch);

    const long long CTX_ELEMS  = (long long)BB * S * DD;
    const long long ATTN_ELEMS = (long long)BH * S * S;
    float* attn = ((long long)out_size >= CTX_ELEMS + ATTN_ELEMS)
                      ? (ctx + CTX_ELEMS) : attn_fallback;

    const int PROJ_SMEM   = 128 * 136 * 4;          // 69632
    const int SCORES_SMEM = 4 * 128 * 72 * 2;       // 73728
    const int AV_SMEM     = (2 * 128 * 72 + 2 * 64 * 72) * 2;  // 55296
    cudaFuncSetAttribute(proj_wmma, cudaFuncAttributeMaxDynamicSharedMemorySize, PROJ_SMEM);
    cudaFuncSetAttribute(scores_wmma, cudaFuncAttributeMaxDynamicSharedMemorySize, SCORES_SMEM);
    cudaFuncSetAttribute(av_wmma, cudaFuncAttributeMaxDynamicSharedMemorySize, AV_SMEM);

    detect_mask_kernel<<<1, 256>>>((const unsigned int*)mask);
    convert_mask_kernel<<<MASK_N / 256, 256>>>(mask, mu8);
    cudaMemsetAsync(rowsum, 0, BH * S * sizeof(float));

    proj_wmma<<<dim3(DD / 128, MROWS / 128, 3), 256, PROJ_SMEM>>>(
        query, key, value, Wq, Wk, Wv, bq, bk, bv, qh, ql, kh, kl, vh, vl);

    scores_wmma<<<dim3(S / 128, S / 128, BH), 256, SCORES_SMEM>>>(
        qh, ql, kh, kl, mu8, attn, rowsum);

    av_wmma<<<dim3(S / 128, BH), 256, AV_SMEM>>>(vh, vl, rowsum, attn, ctx);
}

// round 7
// speedup vs baseline: 1.0785x; 1.0785x over previous
#include <cuda_runtime.h>
#include <cuda_bf16.h>
#include <mma.h>
#include <math_constants.h>

using namespace nvcuda;

// Problem constants
#define BB 2
#define S  2048
#define DD 1024
#define H  16
#define HD 64
#define BH (BB*H)       // 32
#define MROWS (BB*S)    // 4096
#define MASK_N (BB*S*S) // 8,388,608

// Scratch (device globals: allocation-free)
__device__ __nv_bfloat16 g_qh[BH * S * HD];
__device__ __nv_bfloat16 g_ql[BH * S * HD];
__device__ __nv_bfloat16 g_kh[BH * S * HD];
__device__ __nv_bfloat16 g_kl[BH * S * HD];
__device__ __nv_bfloat16 g_vh[BH * S * HD];
__device__ __nv_bfloat16 g_vl[BH * S * HD];
__device__ float g_rowsum[BH * S];
__device__ unsigned char g_mask_u8[MASK_N];
__device__ int g_mask_mode;
__device__ float g_attn_scratch[(size_t)BH * S * S]; // fallback if d_out only holds ctx

// ---------------------------------------------------------------------------
// exp2 on the FMA pipe. Input y = score * log2(e) (scale folded into Q).
// ---------------------------------------------------------------------------
__device__ __forceinline__ float fast_exp2(float y) {
    y = fminf(fmaxf(y, -126.0f), 126.0f);
    float r = rintf(y);
    float f = y - r;                                   // exact
    float p = 1.5403530393381606e-4f;
    p = fmaf(p, f, 1.3333558146428443e-3f);
    p = fmaf(p, f, 9.6181291076284770e-3f);
    p = fmaf(p, f, 5.5504108664821580e-2f);
    p = fmaf(p, f, 2.4022650695910100e-1f);
    p = fmaf(p, f, 6.9314718055994530e-1f);
    p = fmaf(p, f, 1.0f);
    return p * __int_as_float(((int)r + 127) << 23);   // * 2^r
}

__device__ __forceinline__ void split_bf(float x, __nv_bfloat16& h, __nv_bfloat16& l) {
    h = __float2bfloat16(x);
    l = __float2bfloat16(x - __bfloat162float(h));
}
__device__ __forceinline__ unsigned pack2(__nv_bfloat16 a, __nv_bfloat16 b) {
    __nv_bfloat162 t; t.x = a; t.y = b;
    return *(unsigned*)&t;
}

// ---------------------------------------------------------------------------
// Mask dtype detection + conversion (proven R2-R6)
// ---------------------------------------------------------------------------
__global__ void detect_mask_kernel(const unsigned int* __restrict__ w) {
    __shared__ int s_int, s_float;
    if (threadIdx.x == 0) { s_int = 1; s_float = 1; }
    __syncthreads();
    int li = 1, lf = 1;
    for (int i = threadIdx.x; i < 2048; i += 256) {
        unsigned int x = w[i];
        if (x != 0u && x != 1u) li = 0;
        if (x != 0u && x != 0x3f800000u) lf = 0;
    }
    if (!li) atomicAnd(&s_int, 0);
    if (!lf) atomicAnd(&s_float, 0);
    __syncthreads();
    if (threadIdx.x == 0) g_mask_mode = s_int ? 1 : (s_float ? 2 : 0);
}

__global__ void convert_mask_kernel(const void* __restrict__ mraw,
                                    unsigned char* __restrict__ mu8) {
    int i = blockIdx.x * blockDim.x + threadIdx.x;
    if (i >= MASK_N) return;
    int mode = g_mask_mode;
    unsigned char v;
    if (mode == 0)      v = ((const unsigned char*)mraw)[i];
    else if (mode == 1) v = (unsigned char)(((const int*)mraw)[i] != 0);
    else                v = (unsigned char)(((const float*)mraw)[i] != 0.0f);
    mu8[i] = v;
}

// ---------------------------------------------------------------------------
// Projection (all 3 via z): C = X*W^T + bias, *scale, split bf16 hi/lo,
// head-split layout. Q gets scale = 0.125*log2(e) (exp2 folding).
// ---------------------------------------------------------------------------
__global__ void __launch_bounds__(256, 2)
proj_wmma(const float* __restrict__ X0, const float* __restrict__ X1, const float* __restrict__ X2,
          const float* __restrict__ W0, const float* __restrict__ W1, const float* __restrict__ W2,
          const float* __restrict__ B0, const float* __restrict__ B1, const float* __restrict__ B2,
          __nv_bfloat16* __restrict__ Oh0, __nv_bfloat16* __restrict__ Ol0,
          __nv_bfloat16* __restrict__ Oh1, __nv_bfloat16* __restrict__ Ol1,
          __nv_bfloat16* __restrict__ Oh2, __nv_bfloat16* __restrict__ Ol2) {
    extern __shared__ char smraw[];
    __nv_bfloat16* sAh = (__nv_bfloat16*)smraw;        // [128][40]
    __nv_bfloat16* sAl = sAh + 128 * 40;
    __nv_bfloat16* sBh = sAl + 128 * 40;
    __nv_bfloat16* sBl = sBh + 128 * 40;
    float* sC = (float*)smraw;                         // [128][136] (aliased)

    const float *X, *W, *Bv; __nv_bfloat16 *Oh, *Ol; float scale;
    if (blockIdx.z == 0)      { X = X0; W = W0; Bv = B0; Oh = Oh0; Ol = Ol0;
                                scale = 0.18033688011111378f; }   // 0.125*log2(e)
    else if (blockIdx.z == 1) { X = X1; W = W1; Bv = B1; Oh = Oh1; Ol = Ol1; scale = 1.0f; }
    else                      { X = X2; W = W2; Bv = B2; Oh = Oh2; Ol = Ol2; scale = 1.0f; }

    const int tid = threadIdx.x;
    const int warp = tid >> 5, wm = warp >> 1, wn = warp & 1;
    const int m0 = blockIdx.y * 128, n0 = blockIdx.x * 128;
    const int lr = tid >> 3, lc = tid & 7;

    wmma::fragment<wmma::accumulator, 16, 16, 16, float> acc[2][4];
#pragma unroll
    for (int i = 0; i < 2; i++)
#pragma unroll
        for (int j = 0; j < 4; j++) wmma::fill_fragment(acc[i][j], 0.0f);

    for (int k0 = 0; k0 < DD; k0 += 32) {
#pragma unroll
        for (int it = 0; it < 4; it++) {
            int r = lr + it * 32;
            float4 xv = *(const float4*)(X + (size_t)(m0 + r) * DD + k0 + lc * 4);
            float4 wv = *(const float4*)(W + (size_t)(n0 + r) * DD + k0 + lc * 4);
            int sa = r * 40 + lc * 4;
            float xs[4] = {xv.x, xv.y, xv.z, xv.w};
            float ws[4] = {wv.x, wv.y, wv.z, wv.w};
#pragma unroll
            for (int j = 0; j < 4; j++) {
                __nv_bfloat16 h, l;
                split_bf(xs[j], h, l); sAh[sa + j] = h; sAl[sa + j] = l;
                split_bf(ws[j], h, l); sBh[sa + j] = h; sBl[sa + j] = l;
            }
        }
        __syncthreads();
#pragma unroll
        for (int kk = 0; kk < 32; kk += 16) {
            wmma::fragment<wmma::matrix_a, 16, 16, 16, __nv_bfloat16, wmma::row_major> ah[2], al[2];
#pragma unroll
            for (int i = 0; i < 2; i++) {
                wmma::load_matrix_sync(ah[i], sAh + (wm * 32 + i * 16) * 40 + kk, 40);
                wmma::load_matrix_sync(al[i], sAl + (wm * 32 + i * 16) * 40 + kk, 40);
            }
#pragma unroll
            for (int j = 0; j < 4; j++) {
                wmma::fragment<wmma::matrix_b, 16, 16, 16, __nv_bfloat16, wmma::col_major> bh_, bl_;
                wmma::load_matrix_sync(bh_, sBh + (wn * 64 + j * 16) * 40 + kk, 40);
                wmma::load_matrix_sync(bl_, sBl + (wn * 64 + j * 16) * 40 + kk, 40);
#pragma unroll
                for (int i = 0; i < 2; i++) {
                    wmma::mma_sync(acc[i][j], ah[i], bh_, acc[i][j]);
                    wmma::mma_sync(acc[i][j], ah[i], bl_, acc[i][j]);
                    wmma::mma_sync(acc[i][j], al[i], bh_, acc[i][j]);
                }
            }
        }
        __syncthreads();
    }

#pragma unroll
    for (int i = 0; i < 2; i++)
#pragma unroll
        for (int j = 0; j < 4; j++)
            wmma::store_matrix_sync(sC + (wm * 32 + i * 16) * 136 + wn * 64 + j * 16,
                                    acc[i][j], 136, wmma::mem_row_major);
    __syncthreads();

#pragma unroll
    for (int it = 0; it < 16; it++) {
        int idx = tid + it * 256;
        int r = idx >> 5, c4 = (idx & 31) * 4;
        float4 v = *(float4*)&sC[r * 136 + c4];
        float4 bb = *(const float4*)&Bv[n0 + c4];
        float o[4] = {(v.x + bb.x) * scale, (v.y + bb.y) * scale,
                      (v.z + bb.z) * scale, (v.w + bb.w) * scale};
        int gc = n0 + c4;
        int hh = gc >> 6, d = gc & 63;
        int gr = m0 + r;
        int b = gr >> 11, s = gr & (S - 1);
        size_t p = (((size_t)(b * H + hh)) * S + s) * HD + d;
        __nv_bfloat16 oh[4], ol[4];
#pragma unroll
        for (int j = 0; j < 4; j++) split_bf(o[j], oh[j], ol[j]);
        uint2 uh, ul;
        uh.x = pack2(oh[0], oh[1]); uh.y = pack2(oh[2], oh[3]);
        ul.x = pack2(ol[0], ol[1]); ul.y = pack2(ol[2], ol[3]);
        *(uint2*)&Oh[p] = uh;
        *(uint2*)&Ol[p] = ul;
    }
}

// ---------------------------------------------------------------------------
// Scores: 128q x 128k tile, d=64 resident. Writes e = mask ? 0 : exp2(Q'.K)
// as RAW fp32 straight into the attn buffer; atomic rowsums.
// (R6-measured: 340us)
// ---------------------------------------------------------------------------
__global__ void __launch_bounds__(256, 2)
scores_wmma(const __nv_bfloat16* __restrict__ Qh, const __nv_bfloat16* __restrict__ Ql,
            const __nv_bfloat16* __restrict__ Kh, const __nv_bfloat16* __restrict__ Kl,
            const unsigned char* __restrict__ mask,
            float* __restrict__ attn, float* __restrict__ rowsum) {
    extern __shared__ char smraw[];
    __nv_bfloat16* sQh = (__nv_bfloat16*)smraw;        // [128][72]
    __nv_bfloat16* sQl = sQh + 128 * 72;
    __nv_bfloat16* sKh = sQl + 128 * 72;
    __nv_bfloat16* sKl = sKh + 128 * 72;
    float* sC = (float*)smraw;                          // [128][136] (aliased)

    const int tid = threadIdx.x;
    const int warp = tid >> 5, wm = warp >> 1, wn = warp & 1;
    const int bh = blockIdx.z;
    const int q0 = blockIdx.y * 128, k0 = blockIdx.x * 128;
    const size_t qb = (size_t)bh * S * HD;
    const int lr = tid >> 3, lc = tid & 7;

#pragma unroll
    for (int it = 0; it < 4; it++) {
        int r = lr + it * 32;
        *(uint4*)&sQh[r * 72 + lc * 8] = *(const uint4*)&Qh[qb + (size_t)(q0 + r) * HD + lc * 8];
        *(uint4*)&sQl[r * 72 + lc * 8] = *(const uint4*)&Ql[qb + (size_t)(q0 + r) * HD + lc * 8];
        *(uint4*)&sKh[r * 72 + lc * 8] = *(const uint4*)&Kh[qb + (size_t)(k0 + r) * HD + lc * 8];
        *(uint4*)&sKl[r * 72 + lc * 8] = *(const uint4*)&Kl[qb + (size_t)(k0 + r) * HD + lc * 8];
    }
    __syncthreads();

    wmma::fragment<wmma::accumulator, 16, 16, 16, float> acc[2][4];
#pragma unroll
    for (int i = 0; i < 2; i++)
#pragma unroll
        for (int j = 0; j < 4; j++) wmma::fill_fragment(acc[i][j], 0.0f);

#pragma unroll
    for (int kk = 0; kk < 64; kk += 16) {
        wmma::fragment<wmma::matrix_a, 16, 16, 16, __nv_bfloat16, wmma::row_major> ah[2], al[2];
#pragma unroll
        for (int i = 0; i < 2; i++) {
            wmma::load_matrix_sync(ah[i], sQh + (wm * 32 + i * 16) * 72 + kk, 72);
            wmma::load_matrix_sync(al[i], sQl + (wm * 32 + i * 16) * 72 + kk, 72);
        }
#pragma unroll
        for (int j = 0; j < 4; j++) {
            wmma::fragment<wmma::matrix_b, 16, 16, 16, __nv_bfloat16, wmma::col_major> bh_, bl_;
            wmma::load_matrix_sync(bh_, sKh + (wn * 64 + j * 16) * 72 + kk, 72);
            wmma::load_matrix_sync(bl_, sKl + (wn * 64 + j * 16) * 72 + kk, 72);
#pragma unroll
            for (int i = 0; i < 2; i++) {
                wmma::mma_sync(acc[i][j], ah[i], bh_, acc[i][j]);
                wmma::mma_sync(acc[i][j], ah[i], bl_, acc[i][j]);
                wmma::mma_sync(acc[i][j], al[i], bh_, acc[i][j]);
            }
        }
    }
    __syncthreads();

#pragma unroll
    for (int i = 0; i < 2; i++)
#pragma unroll
        for (int j = 0; j < 4; j++)
            wmma::store_matrix_sync(sC + (wm * 32 + i * 16) * 136 + wn * 64 + j * 16,
                                    acc[i][j], 136, wmma::mem_row_major);
    __syncthreads();

    const unsigned char* mb = mask + (size_t)(bh & (BB - 1)) * S * S;
    float* ab = attn + (size_t)bh * S * S;
#pragma unroll
    for (int it = 0; it < 16; it++) {
        int idx = tid + it * 256;
        int r = idx >> 5, c4 = (idx & 31) * 4;
        int q = q0 + r, kc = k0 + c4;
        float4 v = *(float4*)&sC[r * 136 + c4];
        uchar4 m4 = *(const uchar4*)&mb[(size_t)q * S + kc];
        float e0 = m4.x ? 0.0f : fast_exp2(v.x);
        float e1 = m4.y ? 0.0f : fast_exp2(v.y);
        float e2 = m4.z ? 0.0f : fast_exp2(v.z);
        float e3 = m4.w ? 0.0f : fast_exp2(v.w);
        *(float4*)&ab[(size_t)q * S + kc] = make_float4(e0, e1, e2, e3);
        float rs = (e0 + e1) + (e2 + e3);
#pragma unroll
        for (int o = 16; o > 0; o >>= 1) rs += __shfl_xor_sync(0xffffffffu, rs, o);
        if ((tid & 31) == 0) atomicAdd(&rowsum[bh * S + q], rs);
    }
}

// ---------------------------------------------------------------------------
// AV (R4-proven tiling): block 128q x 64d, K-step 32, 8 warps as 4x2
// (each warp 32q x 32d, acc[2][2]). A-path: float4 e load -> *rr ->
// float4 attn store (final) -> split once to smem hi/lo.
// ---------------------------------------------------------------------------
__global__ void __launch_bounds__(256, 2)
av_wmma(const __nv_bfloat16* __restrict__ Vh, const __nv_bfloat16* __restrict__ Vl,
        const float* __restrict__ rowsum,
        float* __restrict__ attn, float* __restrict__ ctx) {
    __shared__ __nv_bfloat16 sAh[128 * 40], sAl[128 * 40];
    __shared__ __nv_bfloat16 sVh[32 * 72], sVl[32 * 72];
    __shared__ float rr[128];

    const int tid = threadIdx.x;
    const int warp = tid >> 5, wm = warp >> 1, wn = warp & 1;
    const int bh = blockIdx.y, q0 = blockIdx.x * 128;
    const int b = bh >> 4, h = bh & 15;
    const size_t vb = (size_t)bh * S * HD;
    float* ab = attn + (size_t)bh * S * S;   // block-local base; offsets LOCAL
    const int lr = tid >> 3, lc = tid & 7;

    if (tid < 128) rr[tid] = 1.0f / rowsum[bh * S + q0 + tid];
    __syncthreads();

    wmma::fragment<wmma::accumulator, 16, 16, 16, float> acc[2][2];
#pragma unroll
    for (int i = 0; i < 2; i++)
#pragma unroll
        for (int j = 0; j < 2; j++) wmma::fill_fragment(acc[i][j], 0.0f);

    for (int k0 = 0; k0 < S; k0 += 32) {
        // A: 128q x 32k fp32 -> normalize -> write attn -> split to smem
#pragma unroll
        for (int it = 0; it < 4; it++) {
            int r = lr + it * 32;                    // q row 0..127
            size_t p = (size_t)(q0 + r) * S + k0 + lc * 4;
            float4 e4 = *(const float4*)&ab[p];
            float rrq = rr[r];
            float a0 = e4.x * rrq, a1 = e4.y * rrq, a2 = e4.z * rrq, a3 = e4.w * rrq;
            *(float4*)&ab[p] = make_float4(a0, a1, a2, a3);  // final attn
            __nv_bfloat16 h0, l0, h1, l1, h2, l2, h3, l3;
            split_bf(a0, h0, l0); split_bf(a1, h1, l1);
            split_bf(a2, h2, l2); split_bf(a3, h3, l3);
            uint2 sh, sl;
            sh.x = pack2(h0, h1); sh.y = pack2(h2, h3);
            sl.x = pack2(l0, l1); sl.y = pack2(l2, l3);
            *(uint2*)&sAh[r * 40 + lc * 4] = sh;
            *(uint2*)&sAl[r * 40 + lc * 4] = sl;
        }
        // V: 32k x 64d, uint4 (8 bf16) per access
        {
            int r = tid >> 3, c8 = (tid & 7) * 8;
            *(uint4*)&sVh[r * 72 + c8] = *(const uint4*)&Vh[vb + (size_t)(k0 + r) * HD + c8];
            *(uint4*)&sVl[r * 72 + c8] = *(const uint4*)&Vl[vb + (size_t)(k0 + r) * HD + c8];
        }
        __syncthreads();
#pragma unroll
        for (int kk = 0; kk < 32; kk += 16) {
            wmma::fragment<wmma::matrix_a, 16, 16, 16, __nv_bfloat16, wmma::row_major> ah[2], al[2];
#pragma unroll
            for (int i = 0; i < 2; i++) {
                wmma::load_matrix_sync(ah[i], sAh + (wm * 32 + i * 16) * 40 + kk, 40);
                wmma::load_matrix_sync(al[i], sAl + (wm * 32 + i * 16) * 40 + kk, 40);
            }
#pragma unroll
            for (int j = 0; j < 2; j++) {
                wmma::fragment<wmma::matrix_b, 16, 16, 16, __nv_bfloat16, wmma::row_major> bh_, bl_;
                wmma::load_matrix_sync(bh_, sVh + kk * 72 + wn * 32 + j * 16, 72);
                wmma::load_matrix_sync(bl_, sVl + kk * 72 + wn * 32 + j * 16, 72);
#pragma unroll
                for (int i = 0; i < 2; i++) {
                    wmma::mma_sync(acc[i][j], ah[i], bh_, acc[i][j]);
                    wmma::mma_sync(acc[i][j], ah[i], bl_, acc[i][j]);
                    wmma::mma_sync(acc[i][j], al[i], bh_, acc[i][j]);
                }
            }
        }
        __syncthreads();
    }

#pragma unroll
    for (int i = 0; i < 2; i++)
#pragma unroll
        for (int j = 0; j < 2; j++) {
            int m = q0 + wm * 32 + i * 16;
            int n = wn * 32 + j * 16;
            float* p = ctx + ((size_t)b * S + m) * DD + h * HD + n;
            wmma::store_matrix_sync(p, acc[i][j], DD, wmma::mem_row_major);
        }
}

// ---------------------------------------------------------------------------
extern "C" void kernel_launch(void* const* d_in, const int* in_sizes, int n_in,
                              void* d_out, int out_size) {
    const float* query = (const float*)d_in[0];
    const float* key   = (const float*)d_in[1];
    const float* value = (const float*)d_in[2];
    const void*  mask  = d_in[3];
    const float* Wq = (const float*)d_in[4];
    const float* bq = (const float*)d_in[5];
    const float* Wk = (const float*)d_in[6];
    const float* bk = (const float*)d_in[7];
    const float* Wv = (const float*)d_in[8];
    const float* bv = (const float*)d_in[9];

    float* ctx = (float*)d_out;

    __nv_bfloat16 *qh, *ql, *kh, *kl, *vh, *vl;
    float *rowsum, *attn_fallback;
    unsigned char* mu8;
    cudaGetSymbolAddress((void**)&qh, g_qh);
    cudaGetSymbolAddress((void**)&ql, g_ql);
    cudaGetSymbolAddress((void**)&kh, g_kh);
    cudaGetSymbolAddress((void**)&kl, g_kl);
    cudaGetSymbolAddress((void**)&vh, g_vh);
    cudaGetSymbolAddress((void**)&vl, g_vl);
    cudaGetSymbolAddress((void**)&mu8, g_mask_u8);
    cudaGetSymbolAddress((void**)&rowsum, g_rowsum);
    cudaGetSymbolAddress((void**)&attn_fallback, g_attn_scratch);

    const long long CTX_ELEMS  = (long long)BB * S * DD;
    const long long ATTN_ELEMS = (long long)BH * S * S;
    float* attn = ((long long)out_size >= CTX_ELEMS + ATTN_ELEMS)
                      ? (ctx + CTX_ELEMS) : attn_fallback;

    const int PROJ_SMEM   = 128 * 136 * 4;          // 69632
    const int SCORES_SMEM = 4 * 128 * 72 * 2;       // 73728
    cudaFuncSetAttribute(proj_wmma, cudaFuncAttributeMaxDynamicSharedMemorySize, PROJ_SMEM);
    cudaFuncSetAttribute(scores_wmma, cudaFuncAttributeMaxDynamicSharedMemorySize, SCORES_SMEM);

    detect_mask_kernel<<<1, 256>>>((const unsigned int*)mask);
    convert_mask_kernel<<<MASK_N / 256, 256>>>(mask, mu8);
    cudaMemsetAsync(rowsum, 0, BH * S * sizeof(float));

    proj_wmma<<<dim3(DD / 128, MROWS / 128, 3), 256, PROJ_SMEM>>>(
        query, key, value, Wq, Wk, Wv, bq, bk, bv, qh, ql, kh, kl, vh, vl);

    scores_wmma<<<dim3(S / 128, S / 128, BH), 256, SCORES_SMEM>>>(
        qh, ql, kh, kl, mu8, attn, rowsum);

    av_wmma<<<dim3(S / 128, BH), 256>>>(vh, vl, rowsum, attn, ctx);
}